// round 13
// baseline (speedup 1.0000x reference)
#include <cuda_runtime.h>

// Problem constants
#define G_     2
#define BATCH_ 128
#define L_     2048
#define SD_    64
#define ID_    16
#define OD_    16
#define GB_    (G_*BATCH_)
#define C_     16           // chunks per sequence
#define T_     (L_/C_)      // 128 steps per chunk

// ---------- device scratch (no allocations allowed) ----------
// +8 rows of padding so the scan's branchless ring prefetch never faults
__device__ float g_d[(size_t)GB_*L_*SD_ + 8*SD_];
__device__ float g_FT[G_*SD_*SD_];              // F^T_ per group
__device__ float g_lend[(size_t)GB_*C_*SD_];    // zero-init local chunk-end states
__device__ float g_carry[(size_t)GB_*C_*SD_];   // true incoming state per chunk

// ---------- f32x2 packed helpers ----------
__device__ __forceinline__ unsigned long long pack2(float lo, float hi) {
    unsigned long long r;
    asm("mov.b64 %0, {%1, %2};" : "=l"(r) : "f"(lo), "f"(hi));
    return r;
}
__device__ __forceinline__ void unpack2(unsigned long long v, float& lo, float& hi) {
    asm("mov.b64 {%0, %1}, %2;" : "=f"(lo), "=f"(hi) : "l"(v));
}
__device__ __forceinline__ void fma2(unsigned long long& acc, unsigned long long a, unsigned long long b) {
    asm("fma.rn.f32x2 %0, %1, %2, %0;" : "+l"(acc) : "l"(a), "l"(b));
}
__device__ __forceinline__ void add2(unsigned long long& d, unsigned long long a, unsigned long long b) {
    asm("add.rn.f32x2 %0, %1, %2;" : "=l"(d) : "l"(a), "l"(b));
}

// load a 64-float global row into 32 packed regs (pairs along the row)
__device__ __forceinline__ void load_row64(unsigned long long* m2, const float* row) {
    const float4* r4 = (const float4*)row;
    #pragma unroll
    for (int i = 0; i < 16; i++) {
        float4 v = r4[i];
        m2[2*i]   = pack2(v.x, v.y);
        m2[2*i+1] = pack2(v.z, v.w);
    }
}

// ============================================================================
// K_pow: FT = F^128 via 7 squarings. grid = G_, 512 threads. (proven)
// ============================================================================
__global__ void __launch_bounds__(512) power_kernel(const float* __restrict__ Fm) {
    __shared__ float A[SD_*SD_];
    __shared__ float Bb[SD_*SD_];
    const int g = blockIdx.x, tid = threadIdx.x;
    for (int i = tid; i < SD_*SD_; i += 512) A[i] = Fm[g*SD_*SD_ + i];
    __syncthreads();
    const int r  = tid >> 3;
    const int cq = (tid & 7) * 8;
    #pragma unroll
    for (int it = 0; it < 7; it++) {
        const float* src = (it & 1) ? Bb : A;
        float*       dst = (it & 1) ? A  : Bb;
        float acc[8];
        #pragma unroll
        for (int j = 0; j < 8; j++) acc[j] = 0.f;
        for (int k = 0; k < SD_; k++) {
            float a = src[r*SD_ + k];
            #pragma unroll
            for (int j = 0; j < 8; j++) acc[j] += a * src[k*SD_ + cq + j];
        }
        __syncthreads();
        #pragma unroll
        for (int j = 0; j < 8; j++) dst[r*SD_ + cq + j] = acc[j];
        __syncthreads();
    }
    for (int i = tid; i < SD_*SD_; i += 512) g_FT[g*SD_*SD_ + i] = Bb[i];
}

// ============================================================================
// P1: precolor tiled GEMM, K-SPLIT staging (unchanged from R12 — current best).
// ============================================================================
__global__ void __launch_bounds__(64, 8)
precolor_kernel(const float* __restrict__ wn, const float* __restrict__ inputs,
                const float* __restrict__ SW, const float* __restrict__ Bm)
{
    __shared__ __align__(16) float wT[40][68];     // [k][l] staged half
    __shared__ __align__(16) float SWBt[40][68];   // [k][dim] staged half

    const int tid = threadIdx.x;
    const int lt  = blockIdx.x & 31;
    const int gb  = blockIdx.x >> 5;
    const int g   = gb / BATCH_;
    const int l0  = lt * 64;

    const float4* wrow  = (const float4*)(wn + ((size_t)(l0 + tid)*GB_ + gb)*SD_);
    const float4* urow  = (const float4*)(inputs + ((size_t)gb*L_ + l0 + tid)*ID_);
    const float4* swrow = (const float4*)(SW + ((size_t)g*SD_ + tid)*SD_);
    const float4* brow  = (const float4*)(Bm + ((size_t)g*SD_ + tid)*ID_);

    const int dg = tid >> 3;
    const int lg = tid & 7;

    unsigned long long acc[8][4];
    #pragma unroll
    for (int j = 0; j < 8; j++)
        #pragma unroll
        for (int p = 0; p < 4; p++) acc[j][p] = 0ULL;

    #pragma unroll
    for (int half = 0; half < 2; half++) {
        if (half == 0) {
            #pragma unroll
            for (int i = 0; i < 10; i++) {          // k = 0..39 (w / SW)
                float4 v = wrow[i];
                wT[4*i  ][tid] = v.x; wT[4*i+1][tid] = v.y;
                wT[4*i+2][tid] = v.z; wT[4*i+3][tid] = v.w;
                float4 s = swrow[i];
                SWBt[4*i  ][tid] = s.x; SWBt[4*i+1][tid] = s.y;
                SWBt[4*i+2][tid] = s.z; SWBt[4*i+3][tid] = s.w;
            }
        } else {
            #pragma unroll
            for (int i = 10; i < 16; i++) {         // k = 40..63 -> idx 0..23
                float4 v = wrow[i];
                const int b0 = 4*i - 40;
                wT[b0  ][tid] = v.x; wT[b0+1][tid] = v.y;
                wT[b0+2][tid] = v.z; wT[b0+3][tid] = v.w;
                float4 s = swrow[i];
                SWBt[b0  ][tid] = s.x; SWBt[b0+1][tid] = s.y;
                SWBt[b0+2][tid] = s.z; SWBt[b0+3][tid] = s.w;
            }
            #pragma unroll
            for (int i = 0; i < 4; i++) {           // k = 64..79 -> idx 24..39
                float4 v = urow[i];
                const int b0 = 24 + 4*i;
                wT[b0  ][tid] = v.x; wT[b0+1][tid] = v.y;
                wT[b0+2][tid] = v.z; wT[b0+3][tid] = v.w;
                float4 s = brow[i];
                SWBt[b0  ][tid] = s.x; SWBt[b0+1][tid] = s.y;
                SWBt[b0+2][tid] = s.z; SWBt[b0+3][tid] = s.w;
            }
        }
        __syncthreads();

        #pragma unroll 4
        for (int k = 0; k < 40; k++) {
            float4 ax = *(const float4*)&SWBt[k][dg*8];
            float4 ay = *(const float4*)&SWBt[k][dg*8 + 4];
            unsigned long long s0 = pack2(ax.x, ax.x), s1 = pack2(ax.y, ax.y);
            unsigned long long s2 = pack2(ax.z, ax.z), s3 = pack2(ax.w, ax.w);
            unsigned long long s4 = pack2(ay.x, ay.x), s5 = pack2(ay.y, ay.y);
            unsigned long long s6 = pack2(ay.z, ay.z), s7 = pack2(ay.w, ay.w);
            ulonglong2 bA = *(const ulonglong2*)&wT[k][lg*4];
            ulonglong2 bB = *(const ulonglong2*)&wT[k][32 + lg*4];
            fma2(acc[0][0], s0, bA.x); fma2(acc[0][1], s0, bA.y);
            fma2(acc[0][2], s0, bB.x); fma2(acc[0][3], s0, bB.y);
            fma2(acc[1][0], s1, bA.x); fma2(acc[1][1], s1, bA.y);
            fma2(acc[1][2], s1, bB.x); fma2(acc[1][3], s1, bB.y);
            fma2(acc[2][0], s2, bA.x); fma2(acc[2][1], s2, bA.y);
            fma2(acc[2][2], s2, bB.x); fma2(acc[2][3], s2, bB.y);
            fma2(acc[3][0], s3, bA.x); fma2(acc[3][1], s3, bA.y);
            fma2(acc[3][2], s3, bB.x); fma2(acc[3][3], s3, bB.y);
            fma2(acc[4][0], s4, bA.x); fma2(acc[4][1], s4, bA.y);
            fma2(acc[4][2], s4, bB.x); fma2(acc[4][3], s4, bB.y);
            fma2(acc[5][0], s5, bA.x); fma2(acc[5][1], s5, bA.y);
            fma2(acc[5][2], s5, bB.x); fma2(acc[5][3], s5, bB.y);
            fma2(acc[6][0], s6, bA.x); fma2(acc[6][1], s6, bA.y);
            fma2(acc[6][2], s6, bB.x); fma2(acc[6][3], s6, bB.y);
            fma2(acc[7][0], s7, bA.x); fma2(acc[7][1], s7, bA.y);
            fma2(acc[7][2], s7, bB.x); fma2(acc[7][3], s7, bB.y);
        }
        if (half == 0) __syncthreads();
    }

    float* dbaseA = g_d + ((size_t)gb*L_ + l0 + lg*4)*SD_ + dg*8;
    float* dbaseB = dbaseA + (size_t)32*SD_;
    #pragma unroll
    for (int p = 0; p < 2; p++) {
        float e0,o0,e1,o1,e2,o2,e3,o3,e4,o4,e5,o5,e6,o6,e7,o7;
        unpack2(acc[0][p], e0, o0); unpack2(acc[1][p], e1, o1);
        unpack2(acc[2][p], e2, o2); unpack2(acc[3][p], e3, o3);
        unpack2(acc[4][p], e4, o4); unpack2(acc[5][p], e5, o5);
        unpack2(acc[6][p], e6, o6); unpack2(acc[7][p], e7, o7);
        float4* oute = (float4*)(dbaseA + (size_t)(2*p  )*SD_);
        oute[0] = make_float4(e0, e1, e2, e3);
        oute[1] = make_float4(e4, e5, e6, e7);
        float4* outo = (float4*)(dbaseA + (size_t)(2*p+1)*SD_);
        outo[0] = make_float4(o0, o1, o2, o3);
        outo[1] = make_float4(o4, o5, o6, o7);
    }
    #pragma unroll
    for (int p = 2; p < 4; p++) {
        float e0,o0,e1,o1,e2,o2,e3,o3,e4,o4,e5,o5,e6,o6,e7,o7;
        unpack2(acc[0][p], e0, o0); unpack2(acc[1][p], e1, o1);
        unpack2(acc[2][p], e2, o2); unpack2(acc[3][p], e3, o3);
        unpack2(acc[4][p], e4, o4); unpack2(acc[5][p], e5, o5);
        unpack2(acc[6][p], e6, o6); unpack2(acc[7][p], e7, o7);
        float4* oute = (float4*)(dbaseB + (size_t)(2*(p-2)  )*SD_);
        oute[0] = make_float4(e0, e1, e2, e3);
        oute[1] = make_float4(e4, e5, e6, e7);
        float4* outo = (float4*)(dbaseB + (size_t)(2*(p-2)+1)*SD_);
        outo[0] = make_float4(o0, o1, o2, o3);
        outo[1] = make_float4(o4, o5, o6, o7);
    }
}

// ============================================================================
// SCAN2 (chunked, TWO chunks of the same gb per warp — within-warp ILP;
// F registers shared across both chains). __syncwarp only.
// WRITE=false: local ends; WRITE=true: true states.
// grid = GB*(C_/2) (2048), block = 32. Thread owns dims t and t+32.
// ============================================================================
template<bool WRITE>
__global__ void __launch_bounds__(32)
scan2_kernel(const float* __restrict__ state, const float* __restrict__ Fm,
             float* __restrict__ states_out)
{
    const int t  = threadIdx.x;                 // 0..31
    const int pr = blockIdx.x & (C_/2 - 1);     // 0..7
    const int gb = blockIdx.x >> 3;
    const int g  = gb / BATCH_;
    const int cA = 2*pr, cB = cA + 1;
    const int lA = cA * T_, lB = cB * T_;

    __shared__ __align__(16) float sA[2][SD_];
    __shared__ __align__(16) float sB[2][SD_];

    unsigned long long fa[32], fb[32];
    load_row64(fa, Fm + ((size_t)g*SD_ + t     )*SD_);
    load_row64(fb, Fm + ((size_t)g*SD_ + t + 32)*SD_);

    const float* dA = g_d + ((size_t)gb*L_ + lA)*SD_ + t;
    const float* dB = g_d + ((size_t)gb*L_ + lB)*SD_ + t;
    float* oA = states_out + ((size_t)gb*L_ + lA)*SD_ + t;
    float* oB = states_out + ((size_t)gb*L_ + lB)*SD_ + t;

    // rings, depth 4 per stream (prefetch lead ~4 steps > DRAM latency)
    float rA0[4], rA1[4], rB0[4], rB1[4];
    #pragma unroll
    for (int j = 0; j < 4; j++) {
        rA0[j] = dA[(size_t)j*SD_];      rA1[j] = dA[(size_t)j*SD_ + 32];
        rB0[j] = dB[(size_t)j*SD_];      rB1[j] = dB[(size_t)j*SD_ + 32];
    }

    if (cA == 0) {
        sA[0][t]      = state[(size_t)gb*SD_ + t];
        sA[0][t + 32] = state[(size_t)gb*SD_ + t + 32];
    } else if (WRITE) {
        sA[0][t]      = g_carry[((size_t)gb*C_ + cA)*SD_ + t];
        sA[0][t + 32] = g_carry[((size_t)gb*C_ + cA)*SD_ + t + 32];
    } else {
        sA[0][t]      = 0.f;
        sA[0][t + 32] = 0.f;
    }
    if (WRITE) {
        sB[0][t]      = g_carry[((size_t)gb*C_ + cB)*SD_ + t];
        sB[0][t + 32] = g_carry[((size_t)gb*C_ + cB)*SD_ + t + 32];
    } else {
        sB[0][t]      = 0.f;
        sB[0][t + 32] = 0.f;
    }
    __syncwarp();

    float svA0 = 0.f, svA1 = 0.f, svB0 = 0.f, svB1 = 0.f;
    #pragma unroll 4
    for (int k = 0; k < T_; k++) {
        const int pb = k & 1;
        const float dvA0 = rA0[k & 3], dvA1 = rA1[k & 3];
        const float dvB0 = rB0[k & 3], dvB1 = rB1[k & 3];
        rA0[k & 3] = dA[(size_t)(k + 4)*SD_];
        rA1[k & 3] = dA[(size_t)(k + 4)*SD_ + 32];
        rB0[k & 3] = dB[(size_t)(k + 4)*SD_];      // overruns land in next chunk/pad
        rB1[k & 3] = dB[(size_t)(k + 4)*SD_ + 32];

        // ---- chain A dot (dims t, t+32) ----
        {
            unsigned long long a0=0ULL, a1=0ULL, a2=0ULL, a3=0ULL;
            unsigned long long b0=0ULL, b1=0ULL, b2=0ULL, b3=0ULL;
            const ulonglong2* sp = (const ulonglong2*)sA[pb];
            #pragma unroll
            for (int i = 0; i < 16; i += 2) {
                ulonglong2 va = sp[i], vb = sp[i+1];
                fma2(a0, fa[2*i],   va.x);
                fma2(a1, fa[2*i+1], va.y);
                fma2(a2, fa[2*i+2], vb.x);
                fma2(a3, fa[2*i+3], vb.y);
                fma2(b0, fb[2*i],   va.x);
                fma2(b1, fb[2*i+1], va.y);
                fma2(b2, fb[2*i+2], vb.x);
                fma2(b3, fb[2*i+3], vb.y);
            }
            add2(a0, a0, a1); add2(a2, a2, a3); add2(a0, a0, a2);
            add2(b0, b0, b1); add2(b2, b2, b3); add2(b0, b0, b2);
            float alo, ahi, blo, bhi;
            unpack2(a0, alo, ahi);
            unpack2(b0, blo, bhi);
            svA0 = dvA0 + alo + ahi;
            svA1 = dvA1 + blo + bhi;
        }
        // ---- chain B dot (independent of chain A: fills A's stall gaps) ----
        {
            unsigned long long a0=0ULL, a1=0ULL, a2=0ULL, a3=0ULL;
            unsigned long long b0=0ULL, b1=0ULL, b2=0ULL, b3=0ULL;
            const ulonglong2* sp = (const ulonglong2*)sB[pb];
            #pragma unroll
            for (int i = 0; i < 16; i += 2) {
                ulonglong2 va = sp[i], vb = sp[i+1];
                fma2(a0, fa[2*i],   va.x);
                fma2(a1, fa[2*i+1], va.y);
                fma2(a2, fa[2*i+2], vb.x);
                fma2(a3, fa[2*i+3], vb.y);
                fma2(b0, fb[2*i],   va.x);
                fma2(b1, fb[2*i+1], va.y);
                fma2(b2, fb[2*i+2], vb.x);
                fma2(b3, fb[2*i+3], vb.y);
            }
            add2(a0, a0, a1); add2(a2, a2, a3); add2(a0, a0, a2);
            add2(b0, b0, b1); add2(b2, b2, b3); add2(b0, b0, b2);
            float alo, ahi, blo, bhi;
            unpack2(a0, alo, ahi);
            unpack2(b0, blo, bhi);
            svB0 = dvB0 + alo + ahi;
            svB1 = dvB1 + blo + bhi;
        }

        sA[pb ^ 1][t]      = svA0;
        sA[pb ^ 1][t + 32] = svA1;
        sB[pb ^ 1][t]      = svB0;
        sB[pb ^ 1][t + 32] = svB1;
        if (WRITE) {
            oA[(size_t)k*SD_]      = svA0;
            oA[(size_t)k*SD_ + 32] = svA1;
            oB[(size_t)k*SD_]      = svB0;
            oB[(size_t)k*SD_ + 32] = svB1;
        }
        __syncwarp();
    }

    if (!WRITE) {
        g_lend[((size_t)gb*C_ + cA)*SD_ + t]      = svA0;
        g_lend[((size_t)gb*C_ + cA)*SD_ + t + 32] = svA1;
        g_lend[((size_t)gb*C_ + cB)*SD_ + t]      = svB0;
        g_lend[((size_t)gb*C_ + cB)*SD_ + t + 32] = svB1;
    }
}

// ============================================================================
// carry: te(c) = lend(c) + FT*te(c-1); carry(c) = te(c-1). (unchanged)
// grid = GB (256), block = 32 (1 warp).
// ============================================================================
__global__ void __launch_bounds__(32) carry_kernel()
{
    const int t = threadIdx.x, gb = blockIdx.x, g = gb / BATCH_;
    __shared__ __align__(16) float te_sh[SD_];

    unsigned long long fa[32], fb[32];
    load_row64(fa, g_FT + ((size_t)g*SD_ + t     )*SD_);
    load_row64(fb, g_FT + ((size_t)g*SD_ + t + 32)*SD_);

    const float* lend = g_lend + (size_t)gb*C_*SD_;
    float* carry = g_carry + (size_t)gb*C_*SD_;

    float te0 = lend[t], te1 = lend[t + 32];
    for (int c = 1; c < C_; c++) {
        carry[(size_t)c*SD_ + t]      = te0;
        carry[(size_t)c*SD_ + t + 32] = te1;
        te_sh[t] = te0; te_sh[t + 32] = te1;
        __syncwarp();

        unsigned long long a0=0ULL, a1=0ULL, a2=0ULL, a3=0ULL;
        unsigned long long b0=0ULL, b1=0ULL, b2=0ULL, b3=0ULL;
        const ulonglong2* sp = (const ulonglong2*)te_sh;
        #pragma unroll
        for (int i = 0; i < 16; i += 2) {
            ulonglong2 va = sp[i], vb = sp[i+1];
            fma2(a0, fa[2*i],   va.x);
            fma2(a1, fa[2*i+1], va.y);
            fma2(a2, fa[2*i+2], vb.x);
            fma2(a3, fa[2*i+3], vb.y);
            fma2(b0, fb[2*i],   va.x);
            fma2(b1, fb[2*i+1], va.y);
            fma2(b2, fb[2*i+2], vb.x);
            fma2(b3, fb[2*i+3], vb.y);
        }
        add2(a0, a0, a1); add2(a2, a2, a3); add2(a0, a0, a2);
        add2(b0, b0, b1); add2(b2, b2, b3); add2(b0, b0, b2);
        float alo, ahi, blo, bhi;
        unpack2(a0, alo, ahi);
        unpack2(b0, blo, bhi);
        te0 = lend[(size_t)c*SD_ + t]      + alo + ahi;
        te1 = lend[(size_t)c*SD_ + t + 32] + blo + bhi;
        __syncwarp();
    }
}

// ============================================================================
// P4: obs tiled GEMM, K-SPLIT staging (unchanged from R12 — current best).
// ============================================================================
__global__ void __launch_bounds__(64, 8)
obs_kernel(const float* __restrict__ Hm, const float* __restrict__ SV,
           const float* __restrict__ vn, const float* __restrict__ states_out,
           float* __restrict__ obs_out)
{
    __shared__ __align__(16) float xT[40][132];    // [k][l] staged half
    __shared__ __align__(16) float HSVt[40][16];   // [k][p] staged half

    const int tid = threadIdx.x;
    const int lt  = blockIdx.x & 15;
    const int gb  = blockIdx.x >> 4;
    const int g   = gb / BATCH_;
    const int l0  = lt * 128;

    const int dg = tid >> 4;
    const int lg = tid & 15;

    unsigned long long acc[4][4];
    #pragma unroll
    for (int j = 0; j < 4; j++)
        #pragma unroll
        for (int p = 0; p < 4; p++) acc[j][p] = 0ULL;

    #pragma unroll
    for (int half = 0; half < 2; half++) {
        #pragma unroll
        for (int rr = 0; rr < 2; rr++) {
            const int r = tid + rr*64;
            const float4* srow = (const float4*)(states_out + ((size_t)gb*L_ + l0 + r)*SD_);
            if (half == 0) {
                #pragma unroll
                for (int i = 0; i < 10; i++) {      // s k=0..39
                    float4 v = srow[i];
                    xT[4*i  ][r] = v.x; xT[4*i+1][r] = v.y;
                    xT[4*i+2][r] = v.z; xT[4*i+3][r] = v.w;
                }
            } else {
                #pragma unroll
                for (int i = 10; i < 16; i++) {     // s k=40..63 -> idx 0..23
                    float4 v = srow[i];
                    const int b0 = 4*i - 40;
                    xT[b0  ][r] = v.x; xT[b0+1][r] = v.y;
                    xT[b0+2][r] = v.z; xT[b0+3][r] = v.w;
                }
                const float4* vrow = (const float4*)(vn + ((size_t)(l0 + r)*GB_ + gb)*OD_);
                #pragma unroll
                for (int i = 0; i < 4; i++) {       // v k=64..79 -> idx 24..39
                    float4 v = vrow[i];
                    const int b0 = 24 + 4*i;
                    xT[b0  ][r] = v.x; xT[b0+1][r] = v.y;
                    xT[b0+2][r] = v.z; xT[b0+3][r] = v.w;
                }
            }
        }
        if (tid < 16) {
            const float4* hrow  = (const float4*)(Hm + ((size_t)g*OD_ + tid)*SD_);
            if (half == 0) {
                #pragma unroll
                for (int i = 0; i < 10; i++) {
                    float4 v = hrow[i];
                    HSVt[4*i  ][tid] = v.x; HSVt[4*i+1][tid] = v.y;
                    HSVt[4*i+2][tid] = v.z; HSVt[4*i+3][tid] = v.w;
                }
            } else {
                #pragma unroll
                for (int i = 10; i < 16; i++) {
                    float4 v = hrow[i];
                    const int b0 = 4*i - 40;
                    HSVt[b0  ][tid] = v.x; HSVt[b0+1][tid] = v.y;
                    HSVt[b0+2][tid] = v.z; HSVt[b0+3][tid] = v.w;
                }
                const float4* svrow = (const float4*)(SV + ((size_t)g*OD_ + tid)*OD_);
                #pragma unroll
                for (int i = 0; i < 4; i++) {
                    float4 v = svrow[i];
                    const int b0 = 24 + 4*i;
                    HSVt[b0  ][tid] = v.x; HSVt[b0+1][tid] = v.y;
                    HSVt[b0+2][tid] = v.z; HSVt[b0+3][tid] = v.w;
                }
            }
        }
        __syncthreads();

        #pragma unroll 4
        for (int k = 0; k < 40; k++) {
            float4 a4 = *(const float4*)&HSVt[k][dg*4];
            unsigned long long s0 = pack2(a4.x, a4.x), s1 = pack2(a4.y, a4.y);
            unsigned long long s2 = pack2(a4.z, a4.z), s3 = pack2(a4.w, a4.w);
            ulonglong2 bA = *(const ulonglong2*)&xT[k][lg*4];
            ulonglong2 bB = *(const ulonglong2*)&xT[k][64 + lg*4];
            fma2(acc[0][0], s0, bA.x); fma2(acc[0][1], s0, bA.y);
            fma2(acc[0][2], s0, bB.x); fma2(acc[0][3], s0, bB.y);
            fma2(acc[1][0], s1, bA.x); fma2(acc[1][1], s1, bA.y);
            fma2(acc[1][2], s1, bB.x); fma2(acc[1][3], s1, bB.y);
            fma2(acc[2][0], s2, bA.x); fma2(acc[2][1], s2, bA.y);
            fma2(acc[2][2], s2, bB.x); fma2(acc[2][3], s2, bB.y);
            fma2(acc[3][0], s3, bA.x); fma2(acc[3][1], s3, bA.y);
            fma2(acc[3][2], s3, bB.x); fma2(acc[3][3], s3, bB.y);
        }
        if (half == 0) __syncthreads();
    }

    float* obaseA = obs_out + ((size_t)gb*L_ + l0 + lg*4)*OD_ + dg*4;
    float* obaseB = obaseA + (size_t)64*OD_;
    #pragma unroll
    for (int p = 0; p < 2; p++) {
        float e0,o0,e1,o1,e2,o2,e3,o3;
        unpack2(acc[0][p], e0, o0); unpack2(acc[1][p], e1, o1);
        unpack2(acc[2][p], e2, o2); unpack2(acc[3][p], e3, o3);
        *(float4*)(obaseA + (size_t)(2*p  )*OD_) = make_float4(e0, e1, e2, e3);
        *(float4*)(obaseA + (size_t)(2*p+1)*OD_) = make_float4(o0, o1, o2, o3);
    }
    #pragma unroll
    for (int p = 2; p < 4; p++) {
        float e0,o0,e1,o1,e2,o2,e3,o3;
        unpack2(acc[0][p], e0, o0); unpack2(acc[1][p], e1, o1);
        unpack2(acc[2][p], e2, o2); unpack2(acc[3][p], e3, o3);
        *(float4*)(obaseB + (size_t)(2*(p-2)  )*OD_) = make_float4(e0, e1, e2, e3);
        *(float4*)(obaseB + (size_t)(2*(p-2)+1)*OD_) = make_float4(o0, o1, o2, o3);
    }
}

// ============================================================================
extern "C" void kernel_launch(void* const* d_in, const int* in_sizes, int n_in,
                              void* d_out, int out_size) {
    const float* state  = (const float*)d_in[0];   // [G,B,S]
    const float* inputs = (const float*)d_in[1];   // [G,B,L,I]
    const float* Fm     = (const float*)d_in[2];   // [G,S,S]
    const float* Bm     = (const float*)d_in[3];   // [G,S,I]
    const float* Hm     = (const float*)d_in[4];   // [G,O,S]
    const float* SW     = (const float*)d_in[5];   // [G,S,S]
    const float* SV     = (const float*)d_in[6];   // [G,O,O]
    const float* wn     = (const float*)d_in[7];   // [L,G,B,S]
    const float* vn     = (const float*)d_in[8];   // [L,G,B,O]

    float* states_out = (float*)d_out;                           // [G,B,L,S]
    float* obs_out    = states_out + (size_t)GB_*L_*SD_;         // [G,B,L,O]

    power_kernel   <<<G_, 512>>>(Fm);
    precolor_kernel<<<GB_*32, 64>>>(wn, inputs, SW, Bm);
    scan2_kernel<false><<<GB_*(C_/2), 32>>>(state, Fm, states_out);  // local ends
    carry_kernel   <<<GB_, 32>>>();
    scan2_kernel<true><<<GB_*(C_/2), 32>>>(state, Fm, states_out);   // true states
    obs_kernel     <<<GB_*16, 64>>>(Hm, SV, vn, states_out, obs_out);
}

// round 14
// speedup vs baseline: 1.0585x; 1.0585x over previous
#include <cuda_runtime.h>

// Problem constants
#define G_     2
#define BATCH_ 128
#define L_     2048
#define SD_    64
#define ID_    16
#define OD_    16
#define GB_    (G_*BATCH_)
#define C_     32           // chunks per sequence (R14: 16 -> 32)
#define T_     (L_/C_)      // 64 steps per chunk

// ---------- device scratch (no allocations allowed) ----------
// +8 rows of padding so the scan's branchless ring prefetch never faults
__device__ float g_d[(size_t)GB_*L_*SD_ + 8*SD_];
__device__ float g_FT[G_*SD_*SD_];              // F^T_ per group
__device__ float g_lend[(size_t)GB_*C_*SD_];    // zero-init local chunk-end states
__device__ float g_carry[(size_t)GB_*C_*SD_];   // true incoming state per chunk

// ---------- f32x2 packed helpers ----------
__device__ __forceinline__ unsigned long long pack2(float lo, float hi) {
    unsigned long long r;
    asm("mov.b64 %0, {%1, %2};" : "=l"(r) : "f"(lo), "f"(hi));
    return r;
}
__device__ __forceinline__ void unpack2(unsigned long long v, float& lo, float& hi) {
    asm("mov.b64 {%0, %1}, %2;" : "=f"(lo), "=f"(hi) : "l"(v));
}
__device__ __forceinline__ void fma2(unsigned long long& acc, unsigned long long a, unsigned long long b) {
    asm("fma.rn.f32x2 %0, %1, %2, %0;" : "+l"(acc) : "l"(a), "l"(b));
}
__device__ __forceinline__ void add2(unsigned long long& d, unsigned long long a, unsigned long long b) {
    asm("add.rn.f32x2 %0, %1, %2;" : "=l"(d) : "l"(a), "l"(b));
}

// load a 64-float global row into 32 packed regs (pairs along the row)
__device__ __forceinline__ void load_row64(unsigned long long* m2, const float* row) {
    const float4* r4 = (const float4*)row;
    #pragma unroll
    for (int i = 0; i < 16; i++) {
        float4 v = r4[i];
        m2[2*i]   = pack2(v.x, v.y);
        m2[2*i+1] = pack2(v.z, v.w);
    }
}

// ============================================================================
// K_pow: FT = F^64 via 6 squarings (T_ = 64 = 2^6). grid = G_, 512 threads.
// ============================================================================
__global__ void __launch_bounds__(512) power_kernel(const float* __restrict__ Fm) {
    __shared__ float A[SD_*SD_];
    __shared__ float Bb[SD_*SD_];
    const int g = blockIdx.x, tid = threadIdx.x;
    for (int i = tid; i < SD_*SD_; i += 512) A[i] = Fm[g*SD_*SD_ + i];
    __syncthreads();
    const int r  = tid >> 3;
    const int cq = (tid & 7) * 8;
    #pragma unroll
    for (int it = 0; it < 6; it++) {      // F^2,4,8,16,32,64
        const float* src = (it & 1) ? Bb : A;
        float*       dst = (it & 1) ? A  : Bb;
        float acc[8];
        #pragma unroll
        for (int j = 0; j < 8; j++) acc[j] = 0.f;
        for (int k = 0; k < SD_; k++) {
            float a = src[r*SD_ + k];
            #pragma unroll
            for (int j = 0; j < 8; j++) acc[j] += a * src[k*SD_ + cq + j];
        }
        __syncthreads();
        #pragma unroll
        for (int j = 0; j < 8; j++) dst[r*SD_ + cq + j] = acc[j];
        __syncthreads();
    }
    // 6 iterations -> result in A
    for (int i = tid; i < SD_*SD_; i += 512) g_FT[g*SD_*SD_ + i] = A[i];
}

// ============================================================================
// P1: precolor tiled GEMM, K-SPLIT staging (unchanged from R12 — proven best).
// ============================================================================
__global__ void __launch_bounds__(64, 8)
precolor_kernel(const float* __restrict__ wn, const float* __restrict__ inputs,
                const float* __restrict__ SW, const float* __restrict__ Bm)
{
    __shared__ __align__(16) float wT[40][68];     // [k][l] staged half
    __shared__ __align__(16) float SWBt[40][68];   // [k][dim] staged half

    const int tid = threadIdx.x;
    const int lt  = blockIdx.x & 31;
    const int gb  = blockIdx.x >> 5;
    const int g   = gb / BATCH_;
    const int l0  = lt * 64;

    const float4* wrow  = (const float4*)(wn + ((size_t)(l0 + tid)*GB_ + gb)*SD_);
    const float4* urow  = (const float4*)(inputs + ((size_t)gb*L_ + l0 + tid)*ID_);
    const float4* swrow = (const float4*)(SW + ((size_t)g*SD_ + tid)*SD_);
    const float4* brow  = (const float4*)(Bm + ((size_t)g*SD_ + tid)*ID_);

    const int dg = tid >> 3;
    const int lg = tid & 7;

    unsigned long long acc[8][4];
    #pragma unroll
    for (int j = 0; j < 8; j++)
        #pragma unroll
        for (int p = 0; p < 4; p++) acc[j][p] = 0ULL;

    #pragma unroll
    for (int half = 0; half < 2; half++) {
        if (half == 0) {
            #pragma unroll
            for (int i = 0; i < 10; i++) {          // k = 0..39 (w / SW)
                float4 v = wrow[i];
                wT[4*i  ][tid] = v.x; wT[4*i+1][tid] = v.y;
                wT[4*i+2][tid] = v.z; wT[4*i+3][tid] = v.w;
                float4 s = swrow[i];
                SWBt[4*i  ][tid] = s.x; SWBt[4*i+1][tid] = s.y;
                SWBt[4*i+2][tid] = s.z; SWBt[4*i+3][tid] = s.w;
            }
        } else {
            #pragma unroll
            for (int i = 10; i < 16; i++) {         // k = 40..63 -> idx 0..23
                float4 v = wrow[i];
                const int b0 = 4*i - 40;
                wT[b0  ][tid] = v.x; wT[b0+1][tid] = v.y;
                wT[b0+2][tid] = v.z; wT[b0+3][tid] = v.w;
                float4 s = swrow[i];
                SWBt[b0  ][tid] = s.x; SWBt[b0+1][tid] = s.y;
                SWBt[b0+2][tid] = s.z; SWBt[b0+3][tid] = s.w;
            }
            #pragma unroll
            for (int i = 0; i < 4; i++) {           // k = 64..79 -> idx 24..39
                float4 v = urow[i];
                const int b0 = 24 + 4*i;
                wT[b0  ][tid] = v.x; wT[b0+1][tid] = v.y;
                wT[b0+2][tid] = v.z; wT[b0+3][tid] = v.w;
                float4 s = brow[i];
                SWBt[b0  ][tid] = s.x; SWBt[b0+1][tid] = s.y;
                SWBt[b0+2][tid] = s.z; SWBt[b0+3][tid] = s.w;
            }
        }
        __syncthreads();

        #pragma unroll 4
        for (int k = 0; k < 40; k++) {
            float4 ax = *(const float4*)&SWBt[k][dg*8];
            float4 ay = *(const float4*)&SWBt[k][dg*8 + 4];
            unsigned long long s0 = pack2(ax.x, ax.x), s1 = pack2(ax.y, ax.y);
            unsigned long long s2 = pack2(ax.z, ax.z), s3 = pack2(ax.w, ax.w);
            unsigned long long s4 = pack2(ay.x, ay.x), s5 = pack2(ay.y, ay.y);
            unsigned long long s6 = pack2(ay.z, ay.z), s7 = pack2(ay.w, ay.w);
            ulonglong2 bA = *(const ulonglong2*)&wT[k][lg*4];
            ulonglong2 bB = *(const ulonglong2*)&wT[k][32 + lg*4];
            fma2(acc[0][0], s0, bA.x); fma2(acc[0][1], s0, bA.y);
            fma2(acc[0][2], s0, bB.x); fma2(acc[0][3], s0, bB.y);
            fma2(acc[1][0], s1, bA.x); fma2(acc[1][1], s1, bA.y);
            fma2(acc[1][2], s1, bB.x); fma2(acc[1][3], s1, bB.y);
            fma2(acc[2][0], s2, bA.x); fma2(acc[2][1], s2, bA.y);
            fma2(acc[2][2], s2, bB.x); fma2(acc[2][3], s2, bB.y);
            fma2(acc[3][0], s3, bA.x); fma2(acc[3][1], s3, bA.y);
            fma2(acc[3][2], s3, bB.x); fma2(acc[3][3], s3, bB.y);
            fma2(acc[4][0], s4, bA.x); fma2(acc[4][1], s4, bA.y);
            fma2(acc[4][2], s4, bB.x); fma2(acc[4][3], s4, bB.y);
            fma2(acc[5][0], s5, bA.x); fma2(acc[5][1], s5, bA.y);
            fma2(acc[5][2], s5, bB.x); fma2(acc[5][3], s5, bB.y);
            fma2(acc[6][0], s6, bA.x); fma2(acc[6][1], s6, bA.y);
            fma2(acc[6][2], s6, bB.x); fma2(acc[6][3], s6, bB.y);
            fma2(acc[7][0], s7, bA.x); fma2(acc[7][1], s7, bA.y);
            fma2(acc[7][2], s7, bB.x); fma2(acc[7][3], s7, bB.y);
        }
        if (half == 0) __syncthreads();
    }

    float* dbaseA = g_d + ((size_t)gb*L_ + l0 + lg*4)*SD_ + dg*8;
    float* dbaseB = dbaseA + (size_t)32*SD_;
    #pragma unroll
    for (int p = 0; p < 2; p++) {
        float e0,o0,e1,o1,e2,o2,e3,o3,e4,o4,e5,o5,e6,o6,e7,o7;
        unpack2(acc[0][p], e0, o0); unpack2(acc[1][p], e1, o1);
        unpack2(acc[2][p], e2, o2); unpack2(acc[3][p], e3, o3);
        unpack2(acc[4][p], e4, o4); unpack2(acc[5][p], e5, o5);
        unpack2(acc[6][p], e6, o6); unpack2(acc[7][p], e7, o7);
        float4* oute = (float4*)(dbaseA + (size_t)(2*p  )*SD_);
        oute[0] = make_float4(e0, e1, e2, e3);
        oute[1] = make_float4(e4, e5, e6, e7);
        float4* outo = (float4*)(dbaseA + (size_t)(2*p+1)*SD_);
        outo[0] = make_float4(o0, o1, o2, o3);
        outo[1] = make_float4(o4, o5, o6, o7);
    }
    #pragma unroll
    for (int p = 2; p < 4; p++) {
        float e0,o0,e1,o1,e2,o2,e3,o3,e4,o4,e5,o5,e6,o6,e7,o7;
        unpack2(acc[0][p], e0, o0); unpack2(acc[1][p], e1, o1);
        unpack2(acc[2][p], e2, o2); unpack2(acc[3][p], e3, o3);
        unpack2(acc[4][p], e4, o4); unpack2(acc[5][p], e5, o5);
        unpack2(acc[6][p], e6, o6); unpack2(acc[7][p], e7, o7);
        float4* oute = (float4*)(dbaseB + (size_t)(2*(p-2)  )*SD_);
        oute[0] = make_float4(e0, e1, e2, e3);
        oute[1] = make_float4(e4, e5, e6, e7);
        float4* outo = (float4*)(dbaseB + (size_t)(2*(p-2)+1)*SD_);
        outo[0] = make_float4(o0, o1, o2, o3);
        outo[1] = make_float4(o4, o5, o6, o7);
    }
}

// ============================================================================
// SCAN (chunked, 1 warp per chunk — R12-proven form, __syncwarp only).
// WRITE=false: scanA (lend only); WRITE=true: scanB (true states).
// grid = GB*C_ (8192), block = 32. Thread owns dims t and t+32.
// ============================================================================
template<bool WRITE>
__global__ void __launch_bounds__(32)
scan_chunk_kernel(const float* __restrict__ state, const float* __restrict__ Fm,
                  float* __restrict__ states_out)
{
    const int t  = threadIdx.x;                 // 0..31
    const int c  = blockIdx.x & (C_-1);
    const int gb = blockIdx.x >> 5;             // C_ = 32
    const int g  = gb / BATCH_;
    const int l0 = c * T_;

    __shared__ __align__(16) float s_sh[2][SD_];

    unsigned long long fa[32], fb[32];
    load_row64(fa, Fm + ((size_t)g*SD_ + t     )*SD_);
    load_row64(fb, Fm + ((size_t)g*SD_ + t + 32)*SD_);

    const float* d0 = g_d + ((size_t)gb*L_ + l0)*SD_ + t;
    const float* d1 = d0 + 32;
    float* o0 = states_out + ((size_t)gb*L_ + l0)*SD_ + t;
    float* o1 = o0 + 32;

    float ring0[8], ring1[8];
    #pragma unroll
    for (int j = 0; j < 8; j++) {
        ring0[j] = d0[(size_t)j*SD_];
        ring1[j] = d1[(size_t)j*SD_];
    }

    if (c == 0) {
        s_sh[0][t]      = state[(size_t)gb*SD_ + t];
        s_sh[0][t + 32] = state[(size_t)gb*SD_ + t + 32];
    } else if (WRITE) {
        s_sh[0][t]      = g_carry[((size_t)gb*C_ + c)*SD_ + t];
        s_sh[0][t + 32] = g_carry[((size_t)gb*C_ + c)*SD_ + t + 32];
    } else {
        s_sh[0][t]      = 0.f;
        s_sh[0][t + 32] = 0.f;
    }
    __syncwarp();

    float sv0 = 0.f, sv1 = 0.f;
    #pragma unroll 8
    for (int k = 0; k < T_; k++) {
        const int pb = k & 1;
        const float dv0 = ring0[k & 7];
        const float dv1 = ring1[k & 7];
        ring0[k & 7] = d0[(size_t)(k + 8)*SD_];   // overrun -> next chunk / pad, unused
        ring1[k & 7] = d1[(size_t)(k + 8)*SD_];

        unsigned long long a0=0ULL, a1=0ULL, a2=0ULL, a3=0ULL;
        unsigned long long b0=0ULL, b1=0ULL, b2=0ULL, b3=0ULL;
        const ulonglong2* sp = (const ulonglong2*)s_sh[pb];
        #pragma unroll
        for (int i = 0; i < 16; i += 2) {
            ulonglong2 va = sp[i], vb = sp[i+1];
            fma2(a0, fa[2*i],   va.x);
            fma2(a1, fa[2*i+1], va.y);
            fma2(a2, fa[2*i+2], vb.x);
            fma2(a3, fa[2*i+3], vb.y);
            fma2(b0, fb[2*i],   va.x);
            fma2(b1, fb[2*i+1], va.y);
            fma2(b2, fb[2*i+2], vb.x);
            fma2(b3, fb[2*i+3], vb.y);
        }
        add2(a0, a0, a1); add2(a2, a2, a3); add2(a0, a0, a2);
        add2(b0, b0, b1); add2(b2, b2, b3); add2(b0, b0, b2);
        float alo, ahi, blo, bhi;
        unpack2(a0, alo, ahi);
        unpack2(b0, blo, bhi);
        sv0 = dv0 + alo + ahi;
        sv1 = dv1 + blo + bhi;

        s_sh[pb ^ 1][t]      = sv0;
        s_sh[pb ^ 1][t + 32] = sv1;
        if (WRITE) {
            o0[(size_t)k*SD_] = sv0;
            o1[(size_t)k*SD_] = sv1;
        }
        __syncwarp();
    }

    if (!WRITE) {
        g_lend[((size_t)gb*C_ + c)*SD_ + t]      = sv0;
        g_lend[((size_t)gb*C_ + c)*SD_ + t + 32] = sv1;
    }
}

// ============================================================================
// carry: te(c) = lend(c) + FT*te(c-1); carry(c) = te(c-1).
// grid = GB (256), block = 32 (1 warp). 31 serial steps — still small.
// ============================================================================
__global__ void __launch_bounds__(32) carry_kernel()
{
    const int t = threadIdx.x, gb = blockIdx.x, g = gb / BATCH_;
    __shared__ __align__(16) float te_sh[SD_];

    unsigned long long fa[32], fb[32];
    load_row64(fa, g_FT + ((size_t)g*SD_ + t     )*SD_);
    load_row64(fb, g_FT + ((size_t)g*SD_ + t + 32)*SD_);

    const float* lend = g_lend + (size_t)gb*C_*SD_;
    float* carry = g_carry + (size_t)gb*C_*SD_;

    float te0 = lend[t], te1 = lend[t + 32];
    for (int c = 1; c < C_; c++) {
        carry[(size_t)c*SD_ + t]      = te0;
        carry[(size_t)c*SD_ + t + 32] = te1;
        te_sh[t] = te0; te_sh[t + 32] = te1;
        __syncwarp();

        unsigned long long a0=0ULL, a1=0ULL, a2=0ULL, a3=0ULL;
        unsigned long long b0=0ULL, b1=0ULL, b2=0ULL, b3=0ULL;
        const ulonglong2* sp = (const ulonglong2*)te_sh;
        #pragma unroll
        for (int i = 0; i < 16; i += 2) {
            ulonglong2 va = sp[i], vb = sp[i+1];
            fma2(a0, fa[2*i],   va.x);
            fma2(a1, fa[2*i+1], va.y);
            fma2(a2, fa[2*i+2], vb.x);
            fma2(a3, fa[2*i+3], vb.y);
            fma2(b0, fb[2*i],   va.x);
            fma2(b1, fb[2*i+1], va.y);
            fma2(b2, fb[2*i+2], vb.x);
            fma2(b3, fb[2*i+3], vb.y);
        }
        add2(a0, a0, a1); add2(a2, a2, a3); add2(a0, a0, a2);
        add2(b0, b0, b1); add2(b2, b2, b3); add2(b0, b0, b2);
        float alo, ahi, blo, bhi;
        unpack2(a0, alo, ahi);
        unpack2(b0, blo, bhi);
        te0 = lend[(size_t)c*SD_ + t]      + alo + ahi;
        te1 = lend[(size_t)c*SD_ + t + 32] + blo + bhi;
        __syncwarp();
    }
}

// ============================================================================
// P4: obs tiled GEMM, K-SPLIT staging (unchanged from R12 — proven best).
// ============================================================================
__global__ void __launch_bounds__(64, 8)
obs_kernel(const float* __restrict__ Hm, const float* __restrict__ SV,
           const float* __restrict__ vn, const float* __restrict__ states_out,
           float* __restrict__ obs_out)
{
    __shared__ __align__(16) float xT[40][132];    // [k][l] staged half
    __shared__ __align__(16) float HSVt[40][16];   // [k][p] staged half

    const int tid = threadIdx.x;
    const int lt  = blockIdx.x & 15;
    const int gb  = blockIdx.x >> 4;
    const int g   = gb / BATCH_;
    const int l0  = lt * 128;

    const int dg = tid >> 4;
    const int lg = tid & 15;

    unsigned long long acc[4][4];
    #pragma unroll
    for (int j = 0; j < 4; j++)
        #pragma unroll
        for (int p = 0; p < 4; p++) acc[j][p] = 0ULL;

    #pragma unroll
    for (int half = 0; half < 2; half++) {
        #pragma unroll
        for (int rr = 0; rr < 2; rr++) {
            const int r = tid + rr*64;
            const float4* srow = (const float4*)(states_out + ((size_t)gb*L_ + l0 + r)*SD_);
            if (half == 0) {
                #pragma unroll
                for (int i = 0; i < 10; i++) {      // s k=0..39
                    float4 v = srow[i];
                    xT[4*i  ][r] = v.x; xT[4*i+1][r] = v.y;
                    xT[4*i+2][r] = v.z; xT[4*i+3][r] = v.w;
                }
            } else {
                #pragma unroll
                for (int i = 10; i < 16; i++) {     // s k=40..63 -> idx 0..23
                    float4 v = srow[i];
                    const int b0 = 4*i - 40;
                    xT[b0  ][r] = v.x; xT[b0+1][r] = v.y;
                    xT[b0+2][r] = v.z; xT[b0+3][r] = v.w;
                }
                const float4* vrow = (const float4*)(vn + ((size_t)(l0 + r)*GB_ + gb)*OD_);
                #pragma unroll
                for (int i = 0; i < 4; i++) {       // v k=64..79 -> idx 24..39
                    float4 v = vrow[i];
                    const int b0 = 24 + 4*i;
                    xT[b0  ][r] = v.x; xT[b0+1][r] = v.y;
                    xT[b0+2][r] = v.z; xT[b0+3][r] = v.w;
                }
            }
        }
        if (tid < 16) {
            const float4* hrow  = (const float4*)(Hm + ((size_t)g*OD_ + tid)*SD_);
            if (half == 0) {
                #pragma unroll
                for (int i = 0; i < 10; i++) {
                    float4 v = hrow[i];
                    HSVt[4*i  ][tid] = v.x; HSVt[4*i+1][tid] = v.y;
                    HSVt[4*i+2][tid] = v.z; HSVt[4*i+3][tid] = v.w;
                }
            } else {
                #pragma unroll
                for (int i = 10; i < 16; i++) {
                    float4 v = hrow[i];
                    const int b0 = 4*i - 40;
                    HSVt[b0  ][tid] = v.x; HSVt[b0+1][tid] = v.y;
                    HSVt[b0+2][tid] = v.z; HSVt[b0+3][tid] = v.w;
                }
                const float4* svrow = (const float4*)(SV + ((size_t)g*OD_ + tid)*OD_);
                #pragma unroll
                for (int i = 0; i < 4; i++) {
                    float4 v = svrow[i];
                    const int b0 = 24 + 4*i;
                    HSVt[b0  ][tid] = v.x; HSVt[b0+1][tid] = v.y;
                    HSVt[b0+2][tid] = v.z; HSVt[b0+3][tid] = v.w;
                }
            }
        }
        __syncthreads();

        #pragma unroll 4
        for (int k = 0; k < 40; k++) {
            float4 a4 = *(const float4*)&HSVt[k][dg*4];
            unsigned long long s0 = pack2(a4.x, a4.x), s1 = pack2(a4.y, a4.y);
            unsigned long long s2 = pack2(a4.z, a4.z), s3 = pack2(a4.w, a4.w);
            ulonglong2 bA = *(const ulonglong2*)&xT[k][lg*4];
            ulonglong2 bB = *(const ulonglong2*)&xT[k][64 + lg*4];
            fma2(acc[0][0], s0, bA.x); fma2(acc[0][1], s0, bA.y);
            fma2(acc[0][2], s0, bB.x); fma2(acc[0][3], s0, bB.y);
            fma2(acc[1][0], s1, bA.x); fma2(acc[1][1], s1, bA.y);
            fma2(acc[1][2], s1, bB.x); fma2(acc[1][3], s1, bB.y);
            fma2(acc[2][0], s2, bA.x); fma2(acc[2][1], s2, bA.y);
            fma2(acc[2][2], s2, bB.x); fma2(acc[2][3], s2, bB.y);
            fma2(acc[3][0], s3, bA.x); fma2(acc[3][1], s3, bA.y);
            fma2(acc[3][2], s3, bB.x); fma2(acc[3][3], s3, bB.y);
        }
        if (half == 0) __syncthreads();
    }

    float* obaseA = obs_out + ((size_t)gb*L_ + l0 + lg*4)*OD_ + dg*4;
    float* obaseB = obaseA + (size_t)64*OD_;
    #pragma unroll
    for (int p = 0; p < 2; p++) {
        float e0,o0,e1,o1,e2,o2,e3,o3;
        unpack2(acc[0][p], e0, o0); unpack2(acc[1][p], e1, o1);
        unpack2(acc[2][p], e2, o2); unpack2(acc[3][p], e3, o3);
        *(float4*)(obaseA + (size_t)(2*p  )*OD_) = make_float4(e0, e1, e2, e3);
        *(float4*)(obaseA + (size_t)(2*p+1)*OD_) = make_float4(o0, o1, o2, o3);
    }
    #pragma unroll
    for (int p = 2; p < 4; p++) {
        float e0,o0,e1,o1,e2,o2,e3,o3;
        unpack2(acc[0][p], e0, o0); unpack2(acc[1][p], e1, o1);
        unpack2(acc[2][p], e2, o2); unpack2(acc[3][p], e3, o3);
        *(float4*)(obaseB + (size_t)(2*(p-2)  )*OD_) = make_float4(e0, e1, e2, e3);
        *(float4*)(obaseB + (size_t)(2*(p-2)+1)*OD_) = make_float4(o0, o1, o2, o3);
    }
}

// ============================================================================
extern "C" void kernel_launch(void* const* d_in, const int* in_sizes, int n_in,
                              void* d_out, int out_size) {
    const float* state  = (const float*)d_in[0];   // [G,B,S]
    const float* inputs = (const float*)d_in[1];   // [G,B,L,I]
    const float* Fm     = (const float*)d_in[2];   // [G,S,S]
    const float* Bm     = (const float*)d_in[3];   // [G,S,I]
    const float* Hm     = (const float*)d_in[4];   // [G,O,S]
    const float* SW     = (const float*)d_in[5];   // [G,S,S]
    const float* SV     = (const float*)d_in[6];   // [G,O,O]
    const float* wn     = (const float*)d_in[7];   // [L,G,B,S]
    const float* vn     = (const float*)d_in[8];   // [L,G,B,O]

    float* states_out = (float*)d_out;                           // [G,B,L,S]
    float* obs_out    = states_out + (size_t)GB_*L_*SD_;         // [G,B,L,O]

    power_kernel   <<<G_, 512>>>(Fm);
    precolor_kernel<<<GB_*32, 64>>>(wn, inputs, SW, Bm);
    scan_chunk_kernel<false><<<GB_*C_, 32>>>(state, Fm, states_out);  // local ends
    carry_kernel   <<<GB_, 32>>>();
    scan_chunk_kernel<true><<<GB_*C_, 32>>>(state, Fm, states_out);   // true states
    obs_kernel     <<<GB_*16, 64>>>(Hm, SV, vn, states_out, obs_out);
}

// round 15
// speedup vs baseline: 1.1259x; 1.0637x over previous
#include <cuda_runtime.h>

// Problem constants
#define G_     2
#define BATCH_ 128
#define L_     2048
#define SD_    64
#define ID_    16
#define OD_    16
#define GB_    (G_*BATCH_)
#define C_     16           // chunks per sequence (measured optimum)
#define T_     (L_/C_)      // 128 steps per chunk

// ---------- device scratch (no allocations allowed) ----------
// +8 rows of padding so the scan's branchless ring prefetch never faults
__device__ float g_d[(size_t)GB_*L_*SD_ + 8*SD_];
__device__ float g_FT[G_*SD_*SD_];              // F^T_ per group
__device__ float g_lend[(size_t)GB_*C_*SD_];    // zero-init local chunk-end states
__device__ float g_carry[(size_t)GB_*C_*SD_];   // true incoming state per chunk

// ---------- f32x2 packed helpers ----------
__device__ __forceinline__ unsigned long long pack2(float lo, float hi) {
    unsigned long long r;
    asm("mov.b64 %0, {%1, %2};" : "=l"(r) : "f"(lo), "f"(hi));
    return r;
}
__device__ __forceinline__ void unpack2(unsigned long long v, float& lo, float& hi) {
    asm("mov.b64 {%0, %1}, %2;" : "=f"(lo), "=f"(hi) : "l"(v));
}
__device__ __forceinline__ void fma2(unsigned long long& acc, unsigned long long a, unsigned long long b) {
    asm("fma.rn.f32x2 %0, %1, %2, %0;" : "+l"(acc) : "l"(a), "l"(b));
}
__device__ __forceinline__ void add2(unsigned long long& d, unsigned long long a, unsigned long long b) {
    asm("add.rn.f32x2 %0, %1, %2;" : "=l"(d) : "l"(a), "l"(b));
}

// load a 64-float global row into 32 packed regs (pairs along the row)
__device__ __forceinline__ void load_row64(unsigned long long* m2, const float* row) {
    const float4* r4 = (const float4*)row;
    #pragma unroll
    for (int i = 0; i < 16; i++) {
        float4 v = r4[i];
        m2[2*i]   = pack2(v.x, v.y);
        m2[2*i+1] = pack2(v.z, v.w);
    }
}

// ============================================================================
// K_pow: FT = F^128 via 7 squarings. grid = G_, 512 threads. (proven)
// ============================================================================
__global__ void __launch_bounds__(512) power_kernel(const float* __restrict__ Fm) {
    __shared__ float A[SD_*SD_];
    __shared__ float Bb[SD_*SD_];
    const int g = blockIdx.x, tid = threadIdx.x;
    for (int i = tid; i < SD_*SD_; i += 512) A[i] = Fm[g*SD_*SD_ + i];
    __syncthreads();
    const int r  = tid >> 3;
    const int cq = (tid & 7) * 8;
    #pragma unroll
    for (int it = 0; it < 7; it++) {
        const float* src = (it & 1) ? Bb : A;
        float*       dst = (it & 1) ? A  : Bb;
        float acc[8];
        #pragma unroll
        for (int j = 0; j < 8; j++) acc[j] = 0.f;
        for (int k = 0; k < SD_; k++) {
            float a = src[r*SD_ + k];
            #pragma unroll
            for (int j = 0; j < 8; j++) acc[j] += a * src[k*SD_ + cq + j];
        }
        __syncthreads();
        #pragma unroll
        for (int j = 0; j < 8; j++) dst[r*SD_ + cq + j] = acc[j];
        __syncthreads();
    }
    for (int i = tid; i < SD_*SD_; i += 512) g_FT[g*SD_*SD_ + i] = Bb[i];
}

// ============================================================================
// P1: precolor tiled GEMM, K-SPLIT staging (byte-identical R12 — proven best).
// ============================================================================
__global__ void __launch_bounds__(64, 8)
precolor_kernel(const float* __restrict__ wn, const float* __restrict__ inputs,
                const float* __restrict__ SW, const float* __restrict__ Bm)
{
    __shared__ __align__(16) float wT[40][68];     // [k][l] staged half
    __shared__ __align__(16) float SWBt[40][68];   // [k][dim] staged half

    const int tid = threadIdx.x;
    const int lt  = blockIdx.x & 31;
    const int gb  = blockIdx.x >> 5;
    const int g   = gb / BATCH_;
    const int l0  = lt * 64;

    const float4* wrow  = (const float4*)(wn + ((size_t)(l0 + tid)*GB_ + gb)*SD_);
    const float4* urow  = (const float4*)(inputs + ((size_t)gb*L_ + l0 + tid)*ID_);
    const float4* swrow = (const float4*)(SW + ((size_t)g*SD_ + tid)*SD_);
    const float4* brow  = (const float4*)(Bm + ((size_t)g*SD_ + tid)*ID_);

    const int dg = tid >> 3;
    const int lg = tid & 7;

    unsigned long long acc[8][4];
    #pragma unroll
    for (int j = 0; j < 8; j++)
        #pragma unroll
        for (int p = 0; p < 4; p++) acc[j][p] = 0ULL;

    #pragma unroll
    for (int half = 0; half < 2; half++) {
        if (half == 0) {
            #pragma unroll
            for (int i = 0; i < 10; i++) {          // k = 0..39 (w / SW)
                float4 v = wrow[i];
                wT[4*i  ][tid] = v.x; wT[4*i+1][tid] = v.y;
                wT[4*i+2][tid] = v.z; wT[4*i+3][tid] = v.w;
                float4 s = swrow[i];
                SWBt[4*i  ][tid] = s.x; SWBt[4*i+1][tid] = s.y;
                SWBt[4*i+2][tid] = s.z; SWBt[4*i+3][tid] = s.w;
            }
        } else {
            #pragma unroll
            for (int i = 10; i < 16; i++) {         // k = 40..63 -> idx 0..23
                float4 v = wrow[i];
                const int b0 = 4*i - 40;
                wT[b0  ][tid] = v.x; wT[b0+1][tid] = v.y;
                wT[b0+2][tid] = v.z; wT[b0+3][tid] = v.w;
                float4 s = swrow[i];
                SWBt[b0  ][tid] = s.x; SWBt[b0+1][tid] = s.y;
                SWBt[b0+2][tid] = s.z; SWBt[b0+3][tid] = s.w;
            }
            #pragma unroll
            for (int i = 0; i < 4; i++) {           // k = 64..79 -> idx 24..39
                float4 v = urow[i];
                const int b0 = 24 + 4*i;
                wT[b0  ][tid] = v.x; wT[b0+1][tid] = v.y;
                wT[b0+2][tid] = v.z; wT[b0+3][tid] = v.w;
                float4 s = brow[i];
                SWBt[b0  ][tid] = s.x; SWBt[b0+1][tid] = s.y;
                SWBt[b0+2][tid] = s.z; SWBt[b0+3][tid] = s.w;
            }
        }
        __syncthreads();

        #pragma unroll 4
        for (int k = 0; k < 40; k++) {
            float4 ax = *(const float4*)&SWBt[k][dg*8];
            float4 ay = *(const float4*)&SWBt[k][dg*8 + 4];
            unsigned long long s0 = pack2(ax.x, ax.x), s1 = pack2(ax.y, ax.y);
            unsigned long long s2 = pack2(ax.z, ax.z), s3 = pack2(ax.w, ax.w);
            unsigned long long s4 = pack2(ay.x, ay.x), s5 = pack2(ay.y, ay.y);
            unsigned long long s6 = pack2(ay.z, ay.z), s7 = pack2(ay.w, ay.w);
            ulonglong2 bA = *(const ulonglong2*)&wT[k][lg*4];
            ulonglong2 bB = *(const ulonglong2*)&wT[k][32 + lg*4];
            fma2(acc[0][0], s0, bA.x); fma2(acc[0][1], s0, bA.y);
            fma2(acc[0][2], s0, bB.x); fma2(acc[0][3], s0, bB.y);
            fma2(acc[1][0], s1, bA.x); fma2(acc[1][1], s1, bA.y);
            fma2(acc[1][2], s1, bB.x); fma2(acc[1][3], s1, bB.y);
            fma2(acc[2][0], s2, bA.x); fma2(acc[2][1], s2, bA.y);
            fma2(acc[2][2], s2, bB.x); fma2(acc[2][3], s2, bB.y);
            fma2(acc[3][0], s3, bA.x); fma2(acc[3][1], s3, bA.y);
            fma2(acc[3][2], s3, bB.x); fma2(acc[3][3], s3, bB.y);
            fma2(acc[4][0], s4, bA.x); fma2(acc[4][1], s4, bA.y);
            fma2(acc[4][2], s4, bB.x); fma2(acc[4][3], s4, bB.y);
            fma2(acc[5][0], s5, bA.x); fma2(acc[5][1], s5, bA.y);
            fma2(acc[5][2], s5, bB.x); fma2(acc[5][3], s5, bB.y);
            fma2(acc[6][0], s6, bA.x); fma2(acc[6][1], s6, bA.y);
            fma2(acc[6][2], s6, bB.x); fma2(acc[6][3], s6, bB.y);
            fma2(acc[7][0], s7, bA.x); fma2(acc[7][1], s7, bA.y);
            fma2(acc[7][2], s7, bB.x); fma2(acc[7][3], s7, bB.y);
        }
        if (half == 0) __syncthreads();
    }

    float* dbaseA = g_d + ((size_t)gb*L_ + l0 + lg*4)*SD_ + dg*8;
    float* dbaseB = dbaseA + (size_t)32*SD_;
    #pragma unroll
    for (int p = 0; p < 2; p++) {
        float e0,o0,e1,o1,e2,o2,e3,o3,e4,o4,e5,o5,e6,o6,e7,o7;
        unpack2(acc[0][p], e0, o0); unpack2(acc[1][p], e1, o1);
        unpack2(acc[2][p], e2, o2); unpack2(acc[3][p], e3, o3);
        unpack2(acc[4][p], e4, o4); unpack2(acc[5][p], e5, o5);
        unpack2(acc[6][p], e6, o6); unpack2(acc[7][p], e7, o7);
        float4* oute = (float4*)(dbaseA + (size_t)(2*p  )*SD_);
        oute[0] = make_float4(e0, e1, e2, e3);
        oute[1] = make_float4(e4, e5, e6, e7);
        float4* outo = (float4*)(dbaseA + (size_t)(2*p+1)*SD_);
        outo[0] = make_float4(o0, o1, o2, o3);
        outo[1] = make_float4(o4, o5, o6, o7);
    }
    #pragma unroll
    for (int p = 2; p < 4; p++) {
        float e0,o0,e1,o1,e2,o2,e3,o3,e4,o4,e5,o5,e6,o6,e7,o7;
        unpack2(acc[0][p], e0, o0); unpack2(acc[1][p], e1, o1);
        unpack2(acc[2][p], e2, o2); unpack2(acc[3][p], e3, o3);
        unpack2(acc[4][p], e4, o4); unpack2(acc[5][p], e5, o5);
        unpack2(acc[6][p], e6, o6); unpack2(acc[7][p], e7, o7);
        float4* oute = (float4*)(dbaseB + (size_t)(2*(p-2)  )*SD_);
        oute[0] = make_float4(e0, e1, e2, e3);
        oute[1] = make_float4(e4, e5, e6, e7);
        float4* outo = (float4*)(dbaseB + (size_t)(2*(p-2)+1)*SD_);
        outo[0] = make_float4(o0, o1, o2, o3);
        outo[1] = make_float4(o4, o5, o6, o7);
    }
}

// ============================================================================
// SCAN A: local chunk-end states only. Skips chunk C-1 (its lend is dead).
// grid = GB*(C_-1), block = 32. Thread owns dims t and t+32. __syncwarp only.
// ============================================================================
__global__ void __launch_bounds__(32)
scanA_kernel(const float* __restrict__ state, const float* __restrict__ Fm)
{
    const int t   = threadIdx.x;                // 0..31
    const int c   = blockIdx.x % (C_-1);        // 0..C_-2 (skip last chunk)
    const int gb  = blockIdx.x / (C_-1);
    const int g   = gb / BATCH_;
    const int l0  = c * T_;

    __shared__ __align__(16) float s_sh[2][SD_];

    unsigned long long fa[32], fb[32];
    load_row64(fa, Fm + ((size_t)g*SD_ + t     )*SD_);
    load_row64(fb, Fm + ((size_t)g*SD_ + t + 32)*SD_);

    const float* d0 = g_d + ((size_t)gb*L_ + l0)*SD_ + t;
    const float* d1 = d0 + 32;

    float ring0[8], ring1[8];
    #pragma unroll
    for (int j = 0; j < 8; j++) {
        ring0[j] = d0[(size_t)j*SD_];
        ring1[j] = d1[(size_t)j*SD_];
    }

    if (c == 0) {
        s_sh[0][t]      = state[(size_t)gb*SD_ + t];
        s_sh[0][t + 32] = state[(size_t)gb*SD_ + t + 32];
    } else {
        s_sh[0][t]      = 0.f;
        s_sh[0][t + 32] = 0.f;
    }
    __syncwarp();

    float sv0 = 0.f, sv1 = 0.f;
    #pragma unroll 8
    for (int k = 0; k < T_; k++) {
        const int pb = k & 1;
        const float dv0 = ring0[k & 7];
        const float dv1 = ring1[k & 7];
        ring0[k & 7] = d0[(size_t)(k + 8)*SD_];   // overrun -> next chunk / pad, unused
        ring1[k & 7] = d1[(size_t)(k + 8)*SD_];

        unsigned long long a0=0ULL, a1=0ULL, a2=0ULL, a3=0ULL;
        unsigned long long b0=0ULL, b1=0ULL, b2=0ULL, b3=0ULL;
        const ulonglong2* sp = (const ulonglong2*)s_sh[pb];
        #pragma unroll
        for (int i = 0; i < 16; i += 2) {
            ulonglong2 va = sp[i], vb = sp[i+1];
            fma2(a0, fa[2*i],   va.x);
            fma2(a1, fa[2*i+1], va.y);
            fma2(a2, fa[2*i+2], vb.x);
            fma2(a3, fa[2*i+3], vb.y);
            fma2(b0, fb[2*i],   va.x);
            fma2(b1, fb[2*i+1], va.y);
            fma2(b2, fb[2*i+2], vb.x);
            fma2(b3, fb[2*i+3], vb.y);
        }
        add2(a0, a0, a1); add2(a2, a2, a3); add2(a0, a0, a2);
        add2(b0, b0, b1); add2(b2, b2, b3); add2(b0, b0, b2);
        float alo, ahi, blo, bhi;
        unpack2(a0, alo, ahi);
        unpack2(b0, blo, bhi);
        sv0 = dv0 + alo + ahi;
        sv1 = dv1 + blo + bhi;

        s_sh[pb ^ 1][t]      = sv0;
        s_sh[pb ^ 1][t + 32] = sv1;
        __syncwarp();
    }

    g_lend[((size_t)gb*C_ + c)*SD_ + t]      = sv0;
    g_lend[((size_t)gb*C_ + c)*SD_ + t + 32] = sv1;
}

// ============================================================================
// SCAN B: true scan with carry init; writes all states.
// grid = GB*C_, block = 32. (byte-identical R12 WRITE=true path)
// ============================================================================
__global__ void __launch_bounds__(32)
scanB_kernel(const float* __restrict__ state, const float* __restrict__ Fm,
             float* __restrict__ states_out)
{
    const int t  = threadIdx.x;                 // 0..31
    const int c  = blockIdx.x & (C_-1);
    const int gb = blockIdx.x >> 4;             // C_ = 16
    const int g  = gb / BATCH_;
    const int l0 = c * T_;

    __shared__ __align__(16) float s_sh[2][SD_];

    unsigned long long fa[32], fb[32];
    load_row64(fa, Fm + ((size_t)g*SD_ + t     )*SD_);
    load_row64(fb, Fm + ((size_t)g*SD_ + t + 32)*SD_);

    const float* d0 = g_d + ((size_t)gb*L_ + l0)*SD_ + t;
    const float* d1 = d0 + 32;
    float* o0 = states_out + ((size_t)gb*L_ + l0)*SD_ + t;
    float* o1 = o0 + 32;

    float ring0[8], ring1[8];
    #pragma unroll
    for (int j = 0; j < 8; j++) {
        ring0[j] = d0[(size_t)j*SD_];
        ring1[j] = d1[(size_t)j*SD_];
    }

    if (c == 0) {
        s_sh[0][t]      = state[(size_t)gb*SD_ + t];
        s_sh[0][t + 32] = state[(size_t)gb*SD_ + t + 32];
    } else {
        s_sh[0][t]      = g_carry[((size_t)gb*C_ + c)*SD_ + t];
        s_sh[0][t + 32] = g_carry[((size_t)gb*C_ + c)*SD_ + t + 32];
    }
    __syncwarp();

    #pragma unroll 8
    for (int k = 0; k < T_; k++) {
        const int pb = k & 1;
        const float dv0 = ring0[k & 7];
        const float dv1 = ring1[k & 7];
        ring0[k & 7] = d0[(size_t)(k + 8)*SD_];
        ring1[k & 7] = d1[(size_t)(k + 8)*SD_];

        unsigned long long a0=0ULL, a1=0ULL, a2=0ULL, a3=0ULL;
        unsigned long long b0=0ULL, b1=0ULL, b2=0ULL, b3=0ULL;
        const ulonglong2* sp = (const ulonglong2*)s_sh[pb];
        #pragma unroll
        for (int i = 0; i < 16; i += 2) {
            ulonglong2 va = sp[i], vb = sp[i+1];
            fma2(a0, fa[2*i],   va.x);
            fma2(a1, fa[2*i+1], va.y);
            fma2(a2, fa[2*i+2], vb.x);
            fma2(a3, fa[2*i+3], vb.y);
            fma2(b0, fb[2*i],   va.x);
            fma2(b1, fb[2*i+1], va.y);
            fma2(b2, fb[2*i+2], vb.x);
            fma2(b3, fb[2*i+3], vb.y);
        }
        add2(a0, a0, a1); add2(a2, a2, a3); add2(a0, a0, a2);
        add2(b0, b0, b1); add2(b2, b2, b3); add2(b0, b0, b2);
        float alo, ahi, blo, bhi;
        unpack2(a0, alo, ahi);
        unpack2(b0, blo, bhi);
        const float sv0 = dv0 + alo + ahi;
        const float sv1 = dv1 + blo + bhi;

        s_sh[pb ^ 1][t]      = sv0;
        s_sh[pb ^ 1][t + 32] = sv1;
        o0[(size_t)k*SD_] = sv0;
        o1[(size_t)k*SD_] = sv1;
        __syncwarp();
    }
}

// ============================================================================
// carry: te(c) = lend(c) + FT*te(c-1); carry(c) = te(c-1).
// grid = GB (256), block = 32. lend prefetched one iteration ahead.
// ============================================================================
__global__ void __launch_bounds__(32) carry_kernel()
{
    const int t = threadIdx.x, gb = blockIdx.x, g = gb / BATCH_;
    __shared__ __align__(16) float te_sh[SD_];

    unsigned long long fa[32], fb[32];
    load_row64(fa, g_FT + ((size_t)g*SD_ + t     )*SD_);
    load_row64(fb, g_FT + ((size_t)g*SD_ + t + 32)*SD_);

    const float* lend = g_lend + (size_t)gb*C_*SD_;
    float* carry = g_carry + (size_t)gb*C_*SD_;

    float te0 = lend[t], te1 = lend[t + 32];          // true end of chunk 0
    float le0 = lend[SD_ + t], le1 = lend[SD_ + t + 32];  // lend(1) prefetched
    for (int c = 1; c < C_; c++) {
        carry[(size_t)c*SD_ + t]      = te0;
        carry[(size_t)c*SD_ + t + 32] = te1;
        te_sh[t] = te0; te_sh[t + 32] = te1;

        // prefetch next iteration's lend BEFORE the dependent dot
        float nle0 = 0.f, nle1 = 0.f;
        if (c + 1 < C_ - 1) {        // lend(C_-1) never written (scanA skips) nor needed
            nle0 = lend[(size_t)(c+1)*SD_ + t];
            nle1 = lend[(size_t)(c+1)*SD_ + t + 32];
        }
        __syncwarp();

        unsigned long long a0=0ULL, a1=0ULL, a2=0ULL, a3=0ULL;
        unsigned long long b0=0ULL, b1=0ULL, b2=0ULL, b3=0ULL;
        const ulonglong2* sp = (const ulonglong2*)te_sh;
        #pragma unroll
        for (int i = 0; i < 16; i += 2) {
            ulonglong2 va = sp[i], vb = sp[i+1];
            fma2(a0, fa[2*i],   va.x);
            fma2(a1, fa[2*i+1], va.y);
            fma2(a2, fa[2*i+2], vb.x);
            fma2(a3, fa[2*i+3], vb.y);
            fma2(b0, fb[2*i],   va.x);
            fma2(b1, fb[2*i+1], va.y);
            fma2(b2, fb[2*i+2], vb.x);
            fma2(b3, fb[2*i+3], vb.y);
        }
        add2(a0, a0, a1); add2(a2, a2, a3); add2(a0, a0, a2);
        add2(b0, b0, b1); add2(b2, b2, b3); add2(b0, b0, b2);
        float alo, ahi, blo, bhi;
        unpack2(a0, alo, ahi);
        unpack2(b0, blo, bhi);
        te0 = le0 + alo + ahi;
        te1 = le1 + blo + bhi;
        le0 = nle0; le1 = nle1;
        __syncwarp();
    }
}

// ============================================================================
// P4: obs tiled GEMM, K-SPLIT staging (byte-identical R12 — proven best).
// ============================================================================
__global__ void __launch_bounds__(64, 8)
obs_kernel(const float* __restrict__ Hm, const float* __restrict__ SV,
           const float* __restrict__ vn, const float* __restrict__ states_out,
           float* __restrict__ obs_out)
{
    __shared__ __align__(16) float xT[40][132];    // [k][l] staged half
    __shared__ __align__(16) float HSVt[40][16];   // [k][p] staged half

    const int tid = threadIdx.x;
    const int lt  = blockIdx.x & 15;
    const int gb  = blockIdx.x >> 4;
    const int g   = gb / BATCH_;
    const int l0  = lt * 128;

    const int dg = tid >> 4;
    const int lg = tid & 15;

    unsigned long long acc[4][4];
    #pragma unroll
    for (int j = 0; j < 4; j++)
        #pragma unroll
        for (int p = 0; p < 4; p++) acc[j][p] = 0ULL;

    #pragma unroll
    for (int half = 0; half < 2; half++) {
        #pragma unroll
        for (int rr = 0; rr < 2; rr++) {
            const int r = tid + rr*64;
            const float4* srow = (const float4*)(states_out + ((size_t)gb*L_ + l0 + r)*SD_);
            if (half == 0) {
                #pragma unroll
                for (int i = 0; i < 10; i++) {      // s k=0..39
                    float4 v = srow[i];
                    xT[4*i  ][r] = v.x; xT[4*i+1][r] = v.y;
                    xT[4*i+2][r] = v.z; xT[4*i+3][r] = v.w;
                }
            } else {
                #pragma unroll
                for (int i = 10; i < 16; i++) {     // s k=40..63 -> idx 0..23
                    float4 v = srow[i];
                    const int b0 = 4*i - 40;
                    xT[b0  ][r] = v.x; xT[b0+1][r] = v.y;
                    xT[b0+2][r] = v.z; xT[b0+3][r] = v.w;
                }
                const float4* vrow = (const float4*)(vn + ((size_t)(l0 + r)*GB_ + gb)*OD_);
                #pragma unroll
                for (int i = 0; i < 4; i++) {       // v k=64..79 -> idx 24..39
                    float4 v = vrow[i];
                    const int b0 = 24 + 4*i;
                    xT[b0  ][r] = v.x; xT[b0+1][r] = v.y;
                    xT[b0+2][r] = v.z; xT[b0+3][r] = v.w;
                }
            }
        }
        if (tid < 16) {
            const float4* hrow  = (const float4*)(Hm + ((size_t)g*OD_ + tid)*SD_);
            if (half == 0) {
                #pragma unroll
                for (int i = 0; i < 10; i++) {
                    float4 v = hrow[i];
                    HSVt[4*i  ][tid] = v.x; HSVt[4*i+1][tid] = v.y;
                    HSVt[4*i+2][tid] = v.z; HSVt[4*i+3][tid] = v.w;
                }
            } else {
                #pragma unroll
                for (int i = 10; i < 16; i++) {
                    float4 v = hrow[i];
                    const int b0 = 4*i - 40;
                    HSVt[b0  ][tid] = v.x; HSVt[b0+1][tid] = v.y;
                    HSVt[b0+2][tid] = v.z; HSVt[b0+3][tid] = v.w;
                }
                const float4* svrow = (const float4*)(SV + ((size_t)g*OD_ + tid)*OD_);
                #pragma unroll
                for (int i = 0; i < 4; i++) {
                    float4 v = svrow[i];
                    const int b0 = 24 + 4*i;
                    HSVt[b0  ][tid] = v.x; HSVt[b0+1][tid] = v.y;
                    HSVt[b0+2][tid] = v.z; HSVt[b0+3][tid] = v.w;
                }
            }
        }
        __syncthreads();

        #pragma unroll 4
        for (int k = 0; k < 40; k++) {
            float4 a4 = *(const float4*)&HSVt[k][dg*4];
            unsigned long long s0 = pack2(a4.x, a4.x), s1 = pack2(a4.y, a4.y);
            unsigned long long s2 = pack2(a4.z, a4.z), s3 = pack2(a4.w, a4.w);
            ulonglong2 bA = *(const ulonglong2*)&xT[k][lg*4];
            ulonglong2 bB = *(const ulonglong2*)&xT[k][64 + lg*4];
            fma2(acc[0][0], s0, bA.x); fma2(acc[0][1], s0, bA.y);
            fma2(acc[0][2], s0, bB.x); fma2(acc[0][3], s0, bB.y);
            fma2(acc[1][0], s1, bA.x); fma2(acc[1][1], s1, bA.y);
            fma2(acc[1][2], s1, bB.x); fma2(acc[1][3], s1, bB.y);
            fma2(acc[2][0], s2, bA.x); fma2(acc[2][1], s2, bA.y);
            fma2(acc[2][2], s2, bB.x); fma2(acc[2][3], s2, bB.y);
            fma2(acc[3][0], s3, bA.x); fma2(acc[3][1], s3, bA.y);
            fma2(acc[3][2], s3, bB.x); fma2(acc[3][3], s3, bB.y);
        }
        if (half == 0) __syncthreads();
    }

    float* obaseA = obs_out + ((size_t)gb*L_ + l0 + lg*4)*OD_ + dg*4;
    float* obaseB = obaseA + (size_t)64*OD_;
    #pragma unroll
    for (int p = 0; p < 2; p++) {
        float e0,o0,e1,o1,e2,o2,e3,o3;
        unpack2(acc[0][p], e0, o0); unpack2(acc[1][p], e1, o1);
        unpack2(acc[2][p], e2, o2); unpack2(acc[3][p], e3, o3);
        *(float4*)(obaseA + (size_t)(2*p  )*OD_) = make_float4(e0, e1, e2, e3);
        *(float4*)(obaseA + (size_t)(2*p+1)*OD_) = make_float4(o0, o1, o2, o3);
    }
    #pragma unroll
    for (int p = 2; p < 4; p++) {
        float e0,o0,e1,o1,e2,o2,e3,o3;
        unpack2(acc[0][p], e0, o0); unpack2(acc[1][p], e1, o1);
        unpack2(acc[2][p], e2, o2); unpack2(acc[3][p], e3, o3);
        *(float4*)(obaseB + (size_t)(2*(p-2)  )*OD_) = make_float4(e0, e1, e2, e3);
        *(float4*)(obaseB + (size_t)(2*(p-2)+1)*OD_) = make_float4(o0, o1, o2, o3);
    }
}

// ============================================================================
extern "C" void kernel_launch(void* const* d_in, const int* in_sizes, int n_in,
                              void* d_out, int out_size) {
    const float* state  = (const float*)d_in[0];   // [G,B,S]
    const float* inputs = (const float*)d_in[1];   // [G,B,L,I]
    const float* Fm     = (const float*)d_in[2];   // [G,S,S]
    const float* Bm     = (const float*)d_in[3];   // [G,S,I]
    const float* Hm     = (const float*)d_in[4];   // [G,O,S]
    const float* SW     = (const float*)d_in[5];   // [G,S,S]
    const float* SV     = (const float*)d_in[6];   // [G,O,O]
    const float* wn     = (const float*)d_in[7];   // [L,G,B,S]
    const float* vn     = (const float*)d_in[8];   // [L,G,B,O]

    float* states_out = (float*)d_out;                           // [G,B,L,S]
    float* obs_out    = states_out + (size_t)GB_*L_*SD_;         // [G,B,L,O]

    power_kernel   <<<G_, 512>>>(Fm);
    precolor_kernel<<<GB_*32, 64>>>(wn, inputs, SW, Bm);
    scanA_kernel   <<<GB_*(C_-1), 32>>>(state, Fm);               // local ends (skip last)
    carry_kernel   <<<GB_, 32>>>();
    scanB_kernel   <<<GB_*C_, 32>>>(state, Fm, states_out);       // true states
    obs_kernel     <<<GB_*16, 64>>>(Hm, SV, vn, states_out, obs_out);
}